// round 5
// baseline (speedup 1.0000x reference)
#include <cuda_runtime.h>

// SGD_Hankel TT-chain: N=65536, L=128, D=4, R=8, O=2.  S=2 samples/thread.
// R5: R2 inner body verbatim (best scheduler result). Changes:
//  - balanced grid: 147 CTAs x 7 warps (448 samples/CTA) -> exactly 1 CTA/SM
//  - x refill double-buffered, drip-fed 2 LDG+STS per step (no exposed DRAM
//    latency burst, one syncwarp per 8 steps)
//  - tail CTA via clamped loads + guarded stores

#define DV 4
#define RV 8
#define LV 128
#define NSTEP 126
#define HALF  63
#define WPC   7                 // warps per CTA
#define SPC   (WPC * 64)        // samples per CTA = 448

typedef unsigned long long u64;

__device__ __forceinline__ u64 fpack(float a, float b) {
    u64 r; asm("mov.b64 %0, {%1,%2};" : "=l"(r) : "f"(a), "f"(b)); return r;
}
__device__ __forceinline__ u64 fdup(float a) {
    u64 r; asm("mov.b64 %0, {%1,%1};" : "=l"(r) : "f"(a)); return r;
}
__device__ __forceinline__ void funpack(u64 v, float& a, float& b) {
    asm("mov.b64 {%0,%1}, %2;" : "=f"(a), "=f"(b) : "l"(v));
}
__device__ __forceinline__ u64 f2mul(u64 a, u64 b) {
    u64 d; asm("mul.rn.f32x2 %0, %1, %2;" : "=l"(d) : "l"(a), "l"(b)); return d;
}
__device__ __forceinline__ u64 f2fma(u64 a, u64 b, u64 c) {
    u64 d; asm("fma.rn.f32x2 %0, %1, %2, %3;" : "=l"(d) : "l"(a), "l"(b), "l"(c)); return d;
}

// smem: cores [63][3][8][8] + xbuf 7 warps * 2 bufs * 2048 + first/last
#define SCORE_FLOATS (HALF * 3 * RV * RV)      // 12096
#define XBUF_FLOATS  (WPC * 2 * 2048)          // 28672
#define SFL_OFF      (SCORE_FLOATS + XBUF_FLOATS)
#define SMEM_FLOATS  (SFL_OFF + 96)
#define SMEM_BYTES   (SMEM_FLOATS * 4)         // 163456

// One refill iteration `it` (0..15): each lane loads one float4 (one sample
// row, one step s8), stores swizzled. Rows 4*it..4*it+3 of the 64-row block.
__device__ __forceinline__ void fill_it(const float* __restrict__ x, float* dstbuf,
                                        int base_w, int lane, int c, int it, int n_clamp)
{
    const int s8 = lane & 7;
    const int g  = lane >> 3;
    const int sw = s8 << 2;
    int r = g + it * 4;
    int n = base_w + ((r & 32) ? (r - 32 + 224) : r);
    n = min(n, n_clamp);
    float4 v = *(const float4*)(x + (size_t)n * (LV * DV) + (c * 8 + s8) * 4);
    int ridx = (r ^ sw) + s8 * 64;
    dstbuf[0 * 512 + ridx] = v.x;
    dstbuf[1 * 512 + ridx] = v.y;
    dstbuf[2 * 512 + ridx] = v.z;
    dstbuf[3 * 512 + ridx] = v.w;
}

extern "C" __global__ void __launch_bounds__(32 * WPC, 1)
tt_chain_kernel(const float* __restrict__ x,
                const float* __restrict__ core_first,
                const float* __restrict__ cores_mid,
                const float* __restrict__ core_last,
                float* __restrict__ out,
                int n_total)
{
    extern __shared__ float sm[];
    float* score  = sm;                    // [63][3][8][8]
    float* xbuf   = sm + SCORE_FLOATS;
    float* sfirst = sm + SFL_OFF;          // 32 floats [j][k]
    float* slast  = sfirst + 32;           // 64 floats [k][j][l]

    const int tid  = threadIdx.x;
    const int lane = tid & 31;
    const int w    = tid >> 5;
    float* xw = xbuf + w * 4096;           // two 2048-float buffers

    const int base_w = blockIdx.x * SPC + w * 32;
    const int n0 = base_w + lane;
    const int n1 = n0 + 224;
    const int n_clamp = n_total - 1;

    // Prime chunk 0 into buffer 0 (overlaps with core staging below).
    #pragma unroll
    for (int it = 0; it < 16; ++it)
        fill_it(x, xw, base_w, lane, 0, it, n_clamp);

    if (tid < 32)       sfirst[tid] = core_first[tid];
    else if (tid < 96)  slast[tid - 32] = core_last[tid - 32];

    u64 mpA[4], mpB[4];
    u64 mdA[8], mdB[8];

    #pragma unroll 1
    for (int phase = 0; phase < 2; ++phase) {
        __syncthreads();    // prior-phase consumers done before core overwrite
        // stage cores for this phase: [s][k][j][l] -> [s][j][k][l], j<3
        for (int u = tid; u < HALF * 48; u += 32 * WPC) {
            int st = u / 48;
            int rr = u - st * 48;
            int j = rr >> 4, k = (rr >> 1) & 7, h = rr & 1;
            float4 v = *(const float4*)(cores_mid
                        + (((size_t)(phase * HALF + st) * RV + k) * DV + j) * RV + h * 4);
            *(float4*)(score + ((st * 3 + j) * RV + k) * RV + h * 4) = v;
        }
        __syncthreads();

        if (phase == 0) {
            // consume l=0 from chunk 0 (s8=0 -> ia=lane), init merged
            float xa0 = xw[lane],        xa1 = xw[512 + lane],
                  xa2 = xw[1024 + lane], xa3 = xw[1536 + lane];
            float xb0 = xw[32 + lane],        xb1 = xw[512 + 32 + lane],
                  xb2 = xw[1024 + 32 + lane], xb3 = xw[1536 + 32 + lane];
            float mA[8], mB[8];
            #pragma unroll
            for (int k = 0; k < 8; ++k) {
                mA[k] = sfirst[k] * xa0 + sfirst[8 + k] * xa1
                      + sfirst[16 + k] * xa2 + sfirst[24 + k] * xa3;
                mB[k] = sfirst[k] * xb0 + sfirst[8 + k] * xb1
                      + sfirst[16 + k] * xb2 + sfirst[24 + k] * xb3;
            }
            #pragma unroll
            for (int p = 0; p < 4; ++p) {
                mpA[p] = fpack(mA[2 * p], mA[2 * p + 1]);
                mpB[p] = fpack(mB[2 * p], mB[2 * p + 1]);
            }
            #pragma unroll
            for (int k = 0; k < 8; ++k) { mdA[k] = fdup(mA[k]); mdB[k] = fdup(mB[k]); }

            // start drip-fill of chunk 1 (iters 0,1) into buffer 1
            fill_it(x, xw + 2048, base_w, lane, 1, 0, n_clamp);
            fill_it(x, xw + 2048, base_w, lane, 1, 1, n_clamp);
        }

        const float* cp = score;
        #pragma unroll 1
        for (int sc = 0; sc < HALF; ++sc) {
            const int l = phase * HALF + sc + 1;       // x index consumed this step
            const int t = l & 7;
            const int c = l >> 3;
            if (t == 0) __syncwarp();                  // publish buffer c&1

            const float* xc = xw + (c & 1) * 2048;
            const int ia = (lane ^ (t << 2)) + t * 64;
            float xa0 = xc[ia],        xa1 = xc[512 + ia],
                  xa2 = xc[1024 + ia], xa3 = xc[1536 + ia];
            float xb0 = xc[32 + ia],        xb1 = xc[512 + 32 + ia],
                  xb2 = xc[1024 + 32 + ia], xb3 = xc[1536 + 32 + ia];

            // drip-fill next chunk (2 iters/step) into the other buffer
            if (c < 15) {
                float* nb = xw + ((c + 1) & 1) * 2048;
                fill_it(x, nb, base_w, lane, c + 1, 2 * t, n_clamp);
                fill_it(x, nb, base_w, lane, c + 1, 2 * t + 1, n_clamp);
            }

            u64 Ya[3][4], Yb[3][4];
            #pragma unroll
            for (int j = 0; j < 3; ++j) {
                const float* cj = cp + j * 64;
                #pragma unroll
                for (int k = 0; k < 8; ++k) {
                    ulonglong2 cA = *(const ulonglong2*)(cj + k * 8);
                    ulonglong2 cB = *(const ulonglong2*)(cj + k * 8 + 4);
                    if (k == 0) {
                        Ya[j][0] = f2mul(mdA[0], cA.x); Ya[j][1] = f2mul(mdA[0], cA.y);
                        Ya[j][2] = f2mul(mdA[0], cB.x); Ya[j][3] = f2mul(mdA[0], cB.y);
                        Yb[j][0] = f2mul(mdB[0], cA.x); Yb[j][1] = f2mul(mdB[0], cA.y);
                        Yb[j][2] = f2mul(mdB[0], cB.x); Yb[j][3] = f2mul(mdB[0], cB.y);
                    } else {
                        Ya[j][0] = f2fma(mdA[k], cA.x, Ya[j][0]);
                        Ya[j][1] = f2fma(mdA[k], cA.y, Ya[j][1]);
                        Ya[j][2] = f2fma(mdA[k], cB.x, Ya[j][2]);
                        Ya[j][3] = f2fma(mdA[k], cB.y, Ya[j][3]);
                        Yb[j][0] = f2fma(mdB[k], cA.x, Yb[j][0]);
                        Yb[j][1] = f2fma(mdB[k], cA.y, Yb[j][1]);
                        Yb[j][2] = f2fma(mdB[k], cB.x, Yb[j][2]);
                        Yb[j][3] = f2fma(mdB[k], cB.y, Yb[j][3]);
                    }
                }
            }

            // identity slice: j=3 term is x3 * merged (exact)
            const u64 a0 = fdup(xa0), a1 = fdup(xa1), a2 = fdup(xa2), a3 = fdup(xa3);
            const u64 b0 = fdup(xb0), b1 = fdup(xb1), b2 = fdup(xb2), b3 = fdup(xb3);
            #pragma unroll
            for (int p = 0; p < 4; ++p) {
                mpA[p] = f2fma(a3, mpA[p],
                         f2fma(a2, Ya[2][p],
                         f2fma(a1, Ya[1][p],
                         f2mul(a0, Ya[0][p]))));
                mpB[p] = f2fma(b3, mpB[p],
                         f2fma(b2, Yb[2][p],
                         f2fma(b1, Yb[1][p],
                         f2mul(b0, Yb[0][p]))));
            }
            // refresh duplicated merged for next step
            #pragma unroll
            for (int p = 0; p < 4; ++p) {
                float u0, u1, v0, v1;
                funpack(mpA[p], u0, u1);
                funpack(mpB[p], v0, v1);
                mdA[2 * p] = fdup(u0); mdA[2 * p + 1] = fdup(u1);
                mdB[2 * p] = fdup(v0); mdB[2 * p + 1] = fdup(v1);
            }
            cp += 192;
        }
    }

    // ---- final contraction: out[l] = sum_j x_j (sum_k m_k core_last[k][j][l]) ----
    {
        const int t = 127 & 7;                 // 7, chunk 15 (buffer 1)
        const float* xc = xw + (15 & 1) * 2048;
        const int ia = (lane ^ (t << 2)) + t * 64;
        float xa0 = xc[ia],        xa1 = xc[512 + ia],
              xa2 = xc[1024 + ia], xa3 = xc[1536 + ia];
        float xb0 = xc[32 + ia],        xb1 = xc[512 + 32 + ia],
              xb2 = xc[1024 + 32 + ia], xb3 = xc[1536 + 32 + ia];

        u64 YlA[4], YlB[4];
        #pragma unroll
        for (int j = 0; j < 4; ++j) {
            u64 accA = f2mul(mdA[0], *(const u64*)(slast + j * 2));
            u64 accB = f2mul(mdB[0], *(const u64*)(slast + j * 2));
            #pragma unroll
            for (int k = 1; k < 8; ++k) {
                u64 cv = *(const u64*)(slast + (k * DV + j) * 2);
                accA = f2fma(mdA[k], cv, accA);
                accB = f2fma(mdB[k], cv, accB);
            }
            YlA[j] = accA; YlB[j] = accB;
        }
        u64 oA = f2fma(fdup(xa3), YlA[3],
                 f2fma(fdup(xa2), YlA[2],
                 f2fma(fdup(xa1), YlA[1],
                 f2mul(fdup(xa0), YlA[0]))));
        u64 oB = f2fma(fdup(xb3), YlB[3],
                 f2fma(fdup(xb2), YlB[2],
                 f2fma(fdup(xb1), YlB[1],
                 f2mul(fdup(xb0), YlB[0]))));
        float r0, r1;
        if (n0 < n_total) {
            funpack(oA, r0, r1);
            float2 res; res.x = r0; res.y = r1;
            *(float2*)(out + 2 * (size_t)n0) = res;
        }
        if (n1 < n_total) {
            funpack(oB, r0, r1);
            float2 res; res.x = r0; res.y = r1;
            *(float2*)(out + 2 * (size_t)n1) = res;
        }
    }
}

extern "C" void kernel_launch(void* const* d_in, const int* in_sizes, int n_in,
                              void* d_out, int out_size)
{
    const float* x  = (const float*)d_in[0];
    const float* cf = (const float*)d_in[1];
    const float* cm = (const float*)d_in[2];
    const float* cl = (const float*)d_in[3];
    float* out = (float*)d_out;

    const int n_total = in_sizes[0] / (LV * DV);   // 65536

    cudaFuncSetAttribute(tt_chain_kernel,
                         cudaFuncAttributeMaxDynamicSharedMemorySize, SMEM_BYTES);

    const int threads = 32 * WPC;                  // 224
    const int blocks = (n_total + SPC - 1) / SPC;  // 147 -> 1 CTA per SM
    tt_chain_kernel<<<blocks, threads, SMEM_BYTES>>>(x, cf, cm, cl, out, n_total);
}

// round 6
// speedup vs baseline: 1.6905x; 1.6905x over previous
#include <cuda_runtime.h>

// SGD_Hankel TT-chain: N=65536, L=128, D=4, R=8, O=2.  S=2 samples/thread.
// R6: exactly R2 (best known body+config, 100.9us) with ONE change: the x
// refill is split so the 16 LDG.128 are issued 8 steps BEFORE their STS
// (register prefetch buffer pv[16]) -> the per-chunk DRAM round-trip is
// fully hidden behind FMA work. Same smem, same occupancy, same body.

#define DV 4
#define RV 8
#define LV 128
#define NSTEP 126
#define HALF  63

typedef unsigned long long u64;

__device__ __forceinline__ u64 fpack(float a, float b) {
    u64 r; asm("mov.b64 %0, {%1,%2};" : "=l"(r) : "f"(a), "f"(b)); return r;
}
__device__ __forceinline__ u64 fdup(float a) {
    u64 r; asm("mov.b64 %0, {%1,%1};" : "=l"(r) : "f"(a)); return r;
}
__device__ __forceinline__ void funpack(u64 v, float& a, float& b) {
    asm("mov.b64 {%0,%1}, %2;" : "=f"(a), "=f"(b) : "l"(v));
}
__device__ __forceinline__ u64 f2mul(u64 a, u64 b) {
    u64 d; asm("mul.rn.f32x2 %0, %1, %2;" : "=l"(d) : "l"(a), "l"(b)); return d;
}
__device__ __forceinline__ u64 f2fma(u64 a, u64 b, u64 c) {
    u64 d; asm("fma.rn.f32x2 %0, %1, %2, %3;" : "=l"(d) : "l"(a), "l"(b), "l"(c)); return d;
}

// smem: phased cores [63][3][8][8] + xbuf 4 warps * 2048 words + first/last
#define SCORE_FLOATS (HALF * 3 * RV * RV)      // 12096
#define XBUF_FLOATS  (4 * 2048)                // 8192
#define SFL_OFF      (SCORE_FLOATS + XBUF_FLOATS)
#define SMEM_FLOATS  (SFL_OFF + 96)
#define SMEM_BYTES   (SMEM_FLOATS * 4)         // 81536

// Issue the 16 coalesced LDG.128 for chunk c into the register buffer.
// (N is an exact multiple of 256 -> no guards.)
__device__ __forceinline__ void ldg_chunk(float4 (&pv)[16], const float* __restrict__ x,
                                          int base_w, int lane, int c)
{
    const int s8 = lane & 7;
    const int g  = lane >> 3;
    #pragma unroll
    for (int it = 0; it < 16; ++it) {
        int r = g + it * 4;                           // local row 0..63
        int n = base_w + ((r & 32) ? (r - 32 + 128) : r);
        pv[it] = *(const float4*)(x + (size_t)n * (LV * DV) + (c * 8 + s8) * 4);
    }
}

// Store the prefetched chunk into the warp's x buffer (swizzled, conflict-free).
__device__ __forceinline__ void sts_chunk(const float4 (&pv)[16], float* xw, int lane)
{
    const int s8 = lane & 7;
    const int g  = lane >> 3;
    const int sw = s8 << 2;
    #pragma unroll
    for (int it = 0; it < 16; ++it) {
        int r = g + it * 4;
        int ridx = (r ^ sw) + s8 * 64;
        xw[0 * 512 + ridx] = pv[it].x;
        xw[1 * 512 + ridx] = pv[it].y;
        xw[2 * 512 + ridx] = pv[it].z;
        xw[3 * 512 + ridx] = pv[it].w;
    }
}

extern "C" __global__ void __launch_bounds__(128, 2)
tt_chain_kernel(const float* __restrict__ x,
                const float* __restrict__ core_first,
                const float* __restrict__ cores_mid,
                const float* __restrict__ core_last,
                float* __restrict__ out,
                int n_total)
{
    extern __shared__ float sm[];
    float* score  = sm;                    // [63][3][8][8]
    float* xbuf   = sm + SCORE_FLOATS;
    float* sfirst = sm + SFL_OFF;          // 32 floats [j][k]
    float* slast  = sfirst + 32;           // 64 floats [k][j][l]

    const int tid  = threadIdx.x;
    const int lane = tid & 31;
    const int w    = tid >> 5;
    float* xw = xbuf + w * 2048;

    const int n0 = blockIdx.x * 256 + tid;
    const int n1 = n0 + 128;
    const int base_w = blockIdx.x * 256 + w * 32;

    float4 pv[16];
    // Prefetch chunk 0 immediately (overlaps core staging + barriers).
    ldg_chunk(pv, x, base_w, lane, 0);

    if (tid < 32)            sfirst[tid] = core_first[tid];
    else if (tid < 96)       slast[tid - 32] = core_last[tid - 32];

    u64 mpA[4], mpB[4];

    #pragma unroll 1
    for (int phase = 0; phase < 2; ++phase) {
        __syncthreads();    // prior-phase consumers done before core overwrite
        // stage cores for this phase: [s][k][j][l] -> [s][j][k][l], j<3
        for (int u = tid; u < HALF * 48; u += 128) {
            int st = u / 48;
            int rr = u - st * 48;
            int j = rr >> 4, k = (rr >> 1) & 7, h = rr & 1;
            float4 v = *(const float4*)(cores_mid
                        + (((size_t)(phase * HALF + st) * RV + k) * DV + j) * RV + h * 4);
            *(float4*)(score + ((st * 3 + j) * RV + k) * RV + h * 4) = v;
        }
        __syncthreads();

        if (phase == 0) {
            // publish chunk 0, start prefetch of chunk 1, init merged from l=0
            sts_chunk(pv, xw, lane);
            __syncwarp();
            ldg_chunk(pv, x, base_w, lane, 1);

            float xa[4], xb[4];
            #pragma unroll
            for (int f = 0; f < 4; ++f) {
                xa[f] = xw[f * 512 + lane];
                xb[f] = xw[f * 512 + 32 + lane];
            }
            float mA[8], mB[8];
            #pragma unroll
            for (int k = 0; k < 8; ++k) {
                mA[k] = sfirst[k] * xa[0] + sfirst[8 + k] * xa[1]
                      + sfirst[16 + k] * xa[2] + sfirst[24 + k] * xa[3];
                mB[k] = sfirst[k] * xb[0] + sfirst[8 + k] * xb[1]
                      + sfirst[16 + k] * xb[2] + sfirst[24 + k] * xb[3];
            }
            #pragma unroll
            for (int p = 0; p < 4; ++p) {
                mpA[p] = fpack(mA[2 * p], mA[2 * p + 1]);
                mpB[p] = fpack(mB[2 * p], mB[2 * p + 1]);
            }
        }

        const float* cp = score;
        #pragma unroll 1
        for (int sc = 0; sc < HALF; ++sc) {
            const int l = phase * HALF + sc + 1;       // x index consumed this step
            if ((l & 7) == 0) {
                // pv holds chunk c=l>>3 (LDG'd 8 steps ago -> data long arrived)
                __syncwarp();                          // close out readers of old chunk
                sts_chunk(pv, xw, lane);
                __syncwarp();                          // publish new chunk
                const int c = l >> 3;
                if (c < 15) ldg_chunk(pv, x, base_w, lane, c + 1);
            }
            const int s8 = l & 7;
            const int ia = (lane ^ (s8 << 2)) + s8 * 64;

            // x reads (issue early to hide LDS latency)
            float xa[4], xb[4];
            #pragma unroll
            for (int f = 0; f < 4; ++f) {
                xa[f] = xw[f * 512 + ia];
                xb[f] = xw[f * 512 + 32 + ia];
            }

            // duplicate merged scalars into packed lanes
            u64 mdA[8], mdB[8];
            #pragma unroll
            for (int p = 0; p < 4; ++p) {
                float a0, a1, b0, b1;
                funpack(mpA[p], a0, a1);
                funpack(mpB[p], b0, b1);
                mdA[2 * p] = fdup(a0); mdA[2 * p + 1] = fdup(a1);
                mdB[2 * p] = fdup(b0); mdB[2 * p + 1] = fdup(b1);
            }

            u64 Ya[3][4], Yb[3][4];
            #pragma unroll
            for (int j = 0; j < 3; ++j) {
                const float* cj = cp + j * 64;
                #pragma unroll
                for (int k = 0; k < 8; ++k) {
                    ulonglong2 cA = *(const ulonglong2*)(cj + k * 8);
                    ulonglong2 cB = *(const ulonglong2*)(cj + k * 8 + 4);
                    if (k == 0) {
                        Ya[j][0] = f2mul(mdA[0], cA.x); Ya[j][1] = f2mul(mdA[0], cA.y);
                        Ya[j][2] = f2mul(mdA[0], cB.x); Ya[j][3] = f2mul(mdA[0], cB.y);
                        Yb[j][0] = f2mul(mdB[0], cA.x); Yb[j][1] = f2mul(mdB[0], cA.y);
                        Yb[j][2] = f2mul(mdB[0], cB.x); Yb[j][3] = f2mul(mdB[0], cB.y);
                    } else {
                        Ya[j][0] = f2fma(mdA[k], cA.x, Ya[j][0]);
                        Ya[j][1] = f2fma(mdA[k], cA.y, Ya[j][1]);
                        Ya[j][2] = f2fma(mdA[k], cB.x, Ya[j][2]);
                        Ya[j][3] = f2fma(mdA[k], cB.y, Ya[j][3]);
                        Yb[j][0] = f2fma(mdB[k], cA.x, Yb[j][0]);
                        Yb[j][1] = f2fma(mdB[k], cA.y, Yb[j][1]);
                        Yb[j][2] = f2fma(mdB[k], cB.x, Yb[j][2]);
                        Yb[j][3] = f2fma(mdB[k], cB.y, Yb[j][3]);
                    }
                }
            }

            // identity slice: j=3 term is x3 * merged (exact)
            const u64 a0 = fdup(xa[0]), a1 = fdup(xa[1]), a2 = fdup(xa[2]), a3 = fdup(xa[3]);
            const u64 b0 = fdup(xb[0]), b1 = fdup(xb[1]), b2 = fdup(xb[2]), b3 = fdup(xb[3]);
            #pragma unroll
            for (int p = 0; p < 4; ++p) {
                mpA[p] = f2fma(a3, mpA[p],
                         f2fma(a2, Ya[2][p],
                         f2fma(a1, Ya[1][p],
                         f2mul(a0, Ya[0][p]))));
                mpB[p] = f2fma(b3, mpB[p],
                         f2fma(b2, Yb[2][p],
                         f2fma(b1, Yb[1][p],
                         f2mul(b0, Yb[0][p]))));
            }
            cp += 3 * 64;
        }
    }

    // ---- final contraction with core_last: out[l] = sum_j x_j (sum_k m_k C[k][j][l]) ----
    {
        const int l = LV - 1;                  // 127, chunk 15 already staged
        const int s8 = l & 7;
        const int ia = (lane ^ (s8 << 2)) + s8 * 64;
        float xa[4], xb[4];
        #pragma unroll
        for (int f = 0; f < 4; ++f) {
            xa[f] = xw[f * 512 + ia];
            xb[f] = xw[f * 512 + 32 + ia];
        }
        u64 mdA[8], mdB[8];
        #pragma unroll
        for (int p = 0; p < 4; ++p) {
            float a0, a1, b0, b1;
            funpack(mpA[p], a0, a1);
            funpack(mpB[p], b0, b1);
            mdA[2 * p] = fdup(a0); mdA[2 * p + 1] = fdup(a1);
            mdB[2 * p] = fdup(b0); mdB[2 * p + 1] = fdup(b1);
        }
        u64 YlA[4], YlB[4];
        #pragma unroll
        for (int j = 0; j < 4; ++j) {
            u64 accA = f2mul(mdA[0], *(const u64*)(slast + j * 2));
            u64 accB = f2mul(mdB[0], *(const u64*)(slast + j * 2));
            #pragma unroll
            for (int k = 1; k < 8; ++k) {
                u64 cv = *(const u64*)(slast + (k * DV + j) * 2);
                accA = f2fma(mdA[k], cv, accA);
                accB = f2fma(mdB[k], cv, accB);
            }
            YlA[j] = accA; YlB[j] = accB;
        }
        u64 oA = f2fma(fdup(xa[3]), YlA[3],
                 f2fma(fdup(xa[2]), YlA[2],
                 f2fma(fdup(xa[1]), YlA[1],
                 f2mul(fdup(xa[0]), YlA[0]))));
        u64 oB = f2fma(fdup(xb[3]), YlB[3],
                 f2fma(fdup(xb[2]), YlB[2],
                 f2fma(fdup(xb[1]), YlB[1],
                 f2mul(fdup(xb[0]), YlB[0]))));
        float r0, r1;
        if (n0 < n_total) {
            funpack(oA, r0, r1);
            float2 res; res.x = r0; res.y = r1;
            *(float2*)(out + 2 * (size_t)n0) = res;
        }
        if (n1 < n_total) {
            funpack(oB, r0, r1);
            float2 res; res.x = r0; res.y = r1;
            *(float2*)(out + 2 * (size_t)n1) = res;
        }
    }
}

extern "C" void kernel_launch(void* const* d_in, const int* in_sizes, int n_in,
                              void* d_out, int out_size)
{
    const float* x  = (const float*)d_in[0];
    const float* cf = (const float*)d_in[1];
    const float* cm = (const float*)d_in[2];
    const float* cl = (const float*)d_in[3];
    float* out = (float*)d_out;

    const int n_total = in_sizes[0] / (LV * DV);   // 65536

    cudaFuncSetAttribute(tt_chain_kernel,
                         cudaFuncAttributeMaxDynamicSharedMemorySize, SMEM_BYTES);

    const int threads = 128;
    const int blocks = (n_total + 255) / 256;      // 2 samples per thread
    tt_chain_kernel<<<blocks, threads, SMEM_BYTES>>>(x, cf, cm, cl, out, n_total);
}

// round 7
// speedup vs baseline: 1.7285x; 1.0225x over previous
#include <cuda_runtime.h>

// SGD_Hankel TT-chain: N=65536, L=128, D=4, R=8, O=2.  S=2 samples/thread.
// R7: R6 (94.7us) with the x-staging path rebuilt on 128-bit ops:
//   - chunk publish: 16 STS.128 (was 64 STS.32)
//   - per-step consume: 2 LDS.128 (was 8 LDS.32)
//   - swizzle pos=(row+s8)&63 (conflict-free for .128 on both sides)
// Core loop, prefetch distance, occupancy identical to R6.

#define DV 4
#define RV 8
#define LV 128
#define NSTEP 126
#define HALF  63

typedef unsigned long long u64;

__device__ __forceinline__ u64 fpack(float a, float b) {
    u64 r; asm("mov.b64 %0, {%1,%2};" : "=l"(r) : "f"(a), "f"(b)); return r;
}
__device__ __forceinline__ u64 fdup(float a) {
    u64 r; asm("mov.b64 %0, {%1,%1};" : "=l"(r) : "f"(a)); return r;
}
__device__ __forceinline__ void funpack(u64 v, float& a, float& b) {
    asm("mov.b64 {%0,%1}, %2;" : "=f"(a), "=f"(b) : "l"(v));
}
__device__ __forceinline__ u64 f2mul(u64 a, u64 b) {
    u64 d; asm("mul.rn.f32x2 %0, %1, %2;" : "=l"(d) : "l"(a), "l"(b)); return d;
}
__device__ __forceinline__ u64 f2fma(u64 a, u64 b, u64 c) {
    u64 d; asm("fma.rn.f32x2 %0, %1, %2, %3;" : "=l"(d) : "l"(a), "l"(b), "l"(c)); return d;
}

// smem: phased cores [63][3][8][8] + xbuf 4 warps * 2048 words + first/last
#define SCORE_FLOATS (HALF * 3 * RV * RV)      // 12096
#define XBUF_FLOATS  (4 * 2048)                // 8192
#define SFL_OFF      (SCORE_FLOATS + XBUF_FLOATS)
#define SMEM_FLOATS  (SFL_OFF + 96)
#define SMEM_BYTES   (SMEM_FLOATS * 4)         // 81536

// Issue the 16 coalesced LDG.128 for chunk c into the register buffer.
// (N is an exact multiple of 256 -> no guards.)
__device__ __forceinline__ void ldg_chunk(float4 (&pv)[16], const float* __restrict__ x,
                                          int base_w, int lane, int c)
{
    const int s8 = lane & 7;
    const int g  = lane >> 3;
    #pragma unroll
    for (int it = 0; it < 16; ++it) {
        int r = g + it * 4;                           // local row 0..63
        int n = base_w + ((r & 32) ? (r - 32 + 128) : r);
        pv[it] = *(const float4*)(x + (size_t)n * (LV * DV) + (c * 8 + s8) * 4);
    }
}

// Publish the prefetched chunk: 16 STS.128, swizzled pos=(r+s8)&63.
// xbuf layout: [s8][pos] float4.
__device__ __forceinline__ void sts_chunk(const float4 (&pv)[16], float* xw, int lane)
{
    const int s8 = lane & 7;
    const int g  = lane >> 3;
    #pragma unroll
    for (int it = 0; it < 16; ++it) {
        int r = g + it * 4;
        int pos = (r + s8) & 63;
        *(float4*)(xw + (s8 * 64 + pos) * 4) = pv[it];
    }
}

extern "C" __global__ void __launch_bounds__(128, 2)
tt_chain_kernel(const float* __restrict__ x,
                const float* __restrict__ core_first,
                const float* __restrict__ cores_mid,
                const float* __restrict__ core_last,
                float* __restrict__ out,
                int n_total)
{
    extern __shared__ float sm[];
    float* score  = sm;                    // [63][3][8][8]
    float* xbuf   = sm + SCORE_FLOATS;
    float* sfirst = sm + SFL_OFF;          // 32 floats [j][k]
    float* slast  = sfirst + 32;           // 64 floats [k][j][l]

    const int tid  = threadIdx.x;
    const int lane = tid & 31;
    const int w    = tid >> 5;
    float* xw = xbuf + w * 2048;

    const int n0 = blockIdx.x * 256 + tid;
    const int n1 = n0 + 128;
    const int base_w = blockIdx.x * 256 + w * 32;

    float4 pv[16];
    // Prefetch chunk 0 immediately (overlaps core staging + barriers).
    ldg_chunk(pv, x, base_w, lane, 0);

    if (tid < 32)            sfirst[tid] = core_first[tid];
    else if (tid < 96)       slast[tid - 32] = core_last[tid - 32];

    u64 mpA[4], mpB[4];

    #pragma unroll 1
    for (int phase = 0; phase < 2; ++phase) {
        __syncthreads();    // prior-phase consumers done before core overwrite
        // stage cores for this phase: [s][k][j][l] -> [s][j][k][l], j<3
        for (int u = tid; u < HALF * 48; u += 128) {
            int st = u / 48;
            int rr = u - st * 48;
            int j = rr >> 4, k = (rr >> 1) & 7, h = rr & 1;
            float4 v = *(const float4*)(cores_mid
                        + (((size_t)(phase * HALF + st) * RV + k) * DV + j) * RV + h * 4);
            *(float4*)(score + ((st * 3 + j) * RV + k) * RV + h * 4) = v;
        }
        __syncthreads();

        if (phase == 0) {
            // publish chunk 0, start prefetch of chunk 1, init merged from l=0
            sts_chunk(pv, xw, lane);
            __syncwarp();
            ldg_chunk(pv, x, base_w, lane, 1);

            // l=0: s8=0 -> pos = row
            float4 xa = *(const float4*)(xw + lane * 4);
            float4 xb = *(const float4*)(xw + (32 + lane) * 4);
            float mA[8], mB[8];
            #pragma unroll
            for (int k = 0; k < 8; ++k) {
                mA[k] = sfirst[k] * xa.x + sfirst[8 + k] * xa.y
                      + sfirst[16 + k] * xa.z + sfirst[24 + k] * xa.w;
                mB[k] = sfirst[k] * xb.x + sfirst[8 + k] * xb.y
                      + sfirst[16 + k] * xb.z + sfirst[24 + k] * xb.w;
            }
            #pragma unroll
            for (int p = 0; p < 4; ++p) {
                mpA[p] = fpack(mA[2 * p], mA[2 * p + 1]);
                mpB[p] = fpack(mB[2 * p], mB[2 * p + 1]);
            }
        }

        const float* cp = score;
        #pragma unroll 1
        for (int sc = 0; sc < HALF; ++sc) {
            const int l = phase * HALF + sc + 1;       // x index consumed this step
            if ((l & 7) == 0) {
                // pv holds chunk c=l>>3 (LDG'd 8 steps ago -> data long arrived)
                __syncwarp();                          // close out readers of old chunk
                sts_chunk(pv, xw, lane);
                __syncwarp();                          // publish new chunk
                const int c = l >> 3;
                if (c < 15) ldg_chunk(pv, x, base_w, lane, c + 1);
            }
            const int s8 = l & 7;

            // x reads: one LDS.128 per sample (issue early to hide latency)
            float4 xa = *(const float4*)(xw + (s8 * 64 + ((lane + s8) & 63)) * 4);
            float4 xb = *(const float4*)(xw + (s8 * 64 + ((lane + 32 + s8) & 63)) * 4);

            // duplicate merged scalars into packed lanes
            u64 mdA[8], mdB[8];
            #pragma unroll
            for (int p = 0; p < 4; ++p) {
                float a0, a1, b0, b1;
                funpack(mpA[p], a0, a1);
                funpack(mpB[p], b0, b1);
                mdA[2 * p] = fdup(a0); mdA[2 * p + 1] = fdup(a1);
                mdB[2 * p] = fdup(b0); mdB[2 * p + 1] = fdup(b1);
            }

            u64 Ya[3][4], Yb[3][4];
            #pragma unroll
            for (int j = 0; j < 3; ++j) {
                const float* cj = cp + j * 64;
                #pragma unroll
                for (int k = 0; k < 8; ++k) {
                    ulonglong2 cA = *(const ulonglong2*)(cj + k * 8);
                    ulonglong2 cB = *(const ulonglong2*)(cj + k * 8 + 4);
                    if (k == 0) {
                        Ya[j][0] = f2mul(mdA[0], cA.x); Ya[j][1] = f2mul(mdA[0], cA.y);
                        Ya[j][2] = f2mul(mdA[0], cB.x); Ya[j][3] = f2mul(mdA[0], cB.y);
                        Yb[j][0] = f2mul(mdB[0], cA.x); Yb[j][1] = f2mul(mdB[0], cA.y);
                        Yb[j][2] = f2mul(mdB[0], cB.x); Yb[j][3] = f2mul(mdB[0], cB.y);
                    } else {
                        Ya[j][0] = f2fma(mdA[k], cA.x, Ya[j][0]);
                        Ya[j][1] = f2fma(mdA[k], cA.y, Ya[j][1]);
                        Ya[j][2] = f2fma(mdA[k], cB.x, Ya[j][2]);
                        Ya[j][3] = f2fma(mdA[k], cB.y, Ya[j][3]);
                        Yb[j][0] = f2fma(mdB[k], cA.x, Yb[j][0]);
                        Yb[j][1] = f2fma(mdB[k], cA.y, Yb[j][1]);
                        Yb[j][2] = f2fma(mdB[k], cB.x, Yb[j][2]);
                        Yb[j][3] = f2fma(mdB[k], cB.y, Yb[j][3]);
                    }
                }
            }

            // identity slice: j=3 term is x3 * merged (exact)
            const u64 a0 = fdup(xa.x), a1 = fdup(xa.y), a2 = fdup(xa.z), a3 = fdup(xa.w);
            const u64 b0 = fdup(xb.x), b1 = fdup(xb.y), b2 = fdup(xb.z), b3 = fdup(xb.w);
            #pragma unroll
            for (int p = 0; p < 4; ++p) {
                mpA[p] = f2fma(a3, mpA[p],
                         f2fma(a2, Ya[2][p],
                         f2fma(a1, Ya[1][p],
                         f2mul(a0, Ya[0][p]))));
                mpB[p] = f2fma(b3, mpB[p],
                         f2fma(b2, Yb[2][p],
                         f2fma(b1, Yb[1][p],
                         f2mul(b0, Yb[0][p]))));
            }
            cp += 3 * 64;
        }
    }

    // ---- final contraction with core_last: out[l] = sum_j x_j (sum_k m_k C[k][j][l]) ----
    {
        const int s8 = 127 & 7;                // 7, chunk 15 already staged
        float4 xa = *(const float4*)(xw + (s8 * 64 + ((lane + s8) & 63)) * 4);
        float4 xb = *(const float4*)(xw + (s8 * 64 + ((lane + 32 + s8) & 63)) * 4);

        u64 mdA[8], mdB[8];
        #pragma unroll
        for (int p = 0; p < 4; ++p) {
            float a0, a1, b0, b1;
            funpack(mpA[p], a0, a1);
            funpack(mpB[p], b0, b1);
            mdA[2 * p] = fdup(a0); mdA[2 * p + 1] = fdup(a1);
            mdB[2 * p] = fdup(b0); mdB[2 * p + 1] = fdup(b1);
        }
        u64 YlA[4], YlB[4];
        #pragma unroll
        for (int j = 0; j < 4; ++j) {
            u64 accA = f2mul(mdA[0], *(const u64*)(slast + j * 2));
            u64 accB = f2mul(mdB[0], *(const u64*)(slast + j * 2));
            #pragma unroll
            for (int k = 1; k < 8; ++k) {
                u64 cv = *(const u64*)(slast + (k * DV + j) * 2);
                accA = f2fma(mdA[k], cv, accA);
                accB = f2fma(mdB[k], cv, accB);
            }
            YlA[j] = accA; YlB[j] = accB;
        }
        u64 oA = f2fma(fdup(xa.w), YlA[3],
                 f2fma(fdup(xa.z), YlA[2],
                 f2fma(fdup(xa.y), YlA[1],
                 f2mul(fdup(xa.x), YlA[0]))));
        u64 oB = f2fma(fdup(xb.w), YlB[3],
                 f2fma(fdup(xb.z), YlB[2],
                 f2fma(fdup(xb.y), YlB[1],
                 f2mul(fdup(xb.x), YlB[0]))));
        float r0, r1;
        if (n0 < n_total) {
            funpack(oA, r0, r1);
            float2 res; res.x = r0; res.y = r1;
            *(float2*)(out + 2 * (size_t)n0) = res;
        }
        if (n1 < n_total) {
            funpack(oB, r0, r1);
            float2 res; res.x = r0; res.y = r1;
            *(float2*)(out + 2 * (size_t)n1) = res;
        }
    }
}

extern "C" void kernel_launch(void* const* d_in, const int* in_sizes, int n_in,
                              void* d_out, int out_size)
{
    const float* x  = (const float*)d_in[0];
    const float* cf = (const float*)d_in[1];
    const float* cm = (const float*)d_in[2];
    const float* cl = (const float*)d_in[3];
    float* out = (float*)d_out;

    const int n_total = in_sizes[0] / (LV * DV);   // 65536

    cudaFuncSetAttribute(tt_chain_kernel,
                         cudaFuncAttributeMaxDynamicSharedMemorySize, SMEM_BYTES);

    const int threads = 128;
    const int blocks = (n_total + 255) / 256;      // 2 samples per thread
    tt_chain_kernel<<<blocks, threads, SMEM_BYTES>>>(x, cf, cm, cl, out, n_total);
}